// round 3
// baseline (speedup 1.0000x reference)
#include <cuda_runtime.h>
#include <cuda_bf16.h>

#define NC 18
#define TPB 256
#define MAX_BLOCKS 16384

// Scratch for deterministic two-stage reduction (no device allocation allowed).
__device__ float g_partials[MAX_BLOCKS];

// loss(row) = -sum_c logsoftmax(x)_c * l_c
//           = (max + log(sum exp(x-max))) * sum(l) - sum(x*l)
__device__ __forceinline__ float row_loss18(const float* __restrict__ x,
                                            const float* __restrict__ l) {
    float m = x[0];
#pragma unroll
    for (int c = 1; c < NC; c++) m = fmaxf(m, x[c]);
    float s = 0.f;
#pragma unroll
    for (int c = 0; c < NC; c++) s += __expf(x[c] - m);
    float sl = 0.f, sxl = 0.f;
#pragma unroll
    for (int c = 0; c < NC; c++) {
        sl += l[c];
        sxl = fmaf(x[c], l[c], sxl);
    }
    return (m + __logf(s)) * sl - sxl;
}

__global__ __launch_bounds__(TPB)
void ce_partial_kernel(const float* __restrict__ X,
                       const float* __restrict__ L,
                       int pairs, int odd) {
    int p = blockIdx.x * TPB + threadIdx.x;
    float acc = 0.f;

    if (p < pairs) {
        // 2 rows = 36 floats = 144 bytes: 16B-aligned for every pair index.
        const float4* __restrict__ x4 =
            reinterpret_cast<const float4*>(X + (size_t)p * (2 * NC));
        const float4* __restrict__ l4 =
            reinterpret_cast<const float4*>(L + (size_t)p * (2 * NC));

        float x[36];
#pragma unroll
        for (int i = 0; i < 9; i++) {
            float4 v = x4[i];
            x[4 * i + 0] = v.x; x[4 * i + 1] = v.y;
            x[4 * i + 2] = v.z; x[4 * i + 3] = v.w;
        }

        // Row statistics from x (still resident in registers).
        float m0 = x[0], m1 = x[18];
#pragma unroll
        for (int c = 1; c < NC; c++) { m0 = fmaxf(m0, x[c]); m1 = fmaxf(m1, x[18 + c]); }
        float s0 = 0.f, s1 = 0.f;
#pragma unroll
        for (int c = 0; c < NC; c++) { s0 += __expf(x[c] - m0); s1 += __expf(x[18 + c] - m1); }

        // Consume labels per-float4 to keep register pressure low.
        float sl0 = 0.f, sxl0 = 0.f, sl1 = 0.f, sxl1 = 0.f;
#pragma unroll
        for (int i = 0; i < 9; i++) {
            float4 v = l4[i];
            float lv[4] = { v.x, v.y, v.z, v.w };
#pragma unroll
            for (int j = 0; j < 4; j++) {
                int idx = 4 * i + j;
                if (idx < NC) { sl0 += lv[j]; sxl0 = fmaf(x[idx], lv[j], sxl0); }
                else          { sl1 += lv[j]; sxl1 = fmaf(x[idx], lv[j], sxl1); }
            }
        }

        acc = (m0 + __logf(s0)) * sl0 - sxl0
            + (m1 + __logf(s1)) * sl1 - sxl1;
    }

    // Odd trailing row (B odd): handled once by thread 0 of block 0.
    if (odd && blockIdx.x == 0 && threadIdx.x == 0) {
        size_t base = (size_t)pairs * (2 * NC);
        float x[NC], l[NC];
#pragma unroll
        for (int c = 0; c < NC; c++) { x[c] = X[base + c]; l[c] = L[base + c]; }
        acc += row_loss18(x, l);
    }

    // Deterministic block reduction: warp shuffle -> smem -> warp 0.
    __shared__ float sdata[TPB / 32];
    int lane = threadIdx.x & 31;
    int wid  = threadIdx.x >> 5;
#pragma unroll
    for (int o = 16; o > 0; o >>= 1) acc += __shfl_down_sync(0xffffffffu, acc, o);
    if (lane == 0) sdata[wid] = acc;
    __syncthreads();
    if (wid == 0) {
        float v = (lane < (TPB / 32)) ? sdata[lane] : 0.f;
#pragma unroll
        for (int o = 16; o > 0; o >>= 1) v += __shfl_down_sync(0xffffffffu, v, o);
        if (lane == 0) g_partials[blockIdx.x] = v;
    }
}

__global__ __launch_bounds__(1024)
void ce_final_kernel(float* __restrict__ out, int nblocks, float inv_b) {
    float acc = 0.f;
    for (int i = threadIdx.x; i < nblocks; i += 1024) acc += g_partials[i];

    __shared__ float sdata[32];
    int lane = threadIdx.x & 31;
    int wid  = threadIdx.x >> 5;
#pragma unroll
    for (int o = 16; o > 0; o >>= 1) acc += __shfl_down_sync(0xffffffffu, acc, o);
    if (lane == 0) sdata[wid] = acc;
    __syncthreads();
    if (wid == 0) {
        float v = (lane < 32) ? sdata[lane] : 0.f;
#pragma unroll
        for (int o = 16; o > 0; o >>= 1) v += __shfl_down_sync(0xffffffffu, v, o);
        if (lane == 0) out[0] = v * inv_b;
    }
}

extern "C" void kernel_launch(void* const* d_in, const int* in_sizes, int n_in,
                              void* d_out, int out_size) {
    const float* X = (const float*)d_in[0];  // output  [B, 18] f32
    const float* L = (const float*)d_in[1];  // labels_soft [B, 18] f32
    float* out = (float*)d_out;

    long long total = in_sizes[0];
    long long B = total / NC;
    int pairs = (int)(B / 2);
    int odd = (int)(B & 1);

    int blocks = (pairs + TPB - 1) / TPB;
    if (blocks < 1) blocks = 1;
    if (blocks > MAX_BLOCKS) blocks = MAX_BLOCKS;  // B=2M -> 3907, well inside

    ce_partial_kernel<<<blocks, TPB>>>(X, L, pairs, odd);
    ce_final_kernel<<<1, 1024>>>(out, blocks, 1.0f / (float)B);
}

// round 5
// speedup vs baseline: 1.3499x; 1.3499x over previous
#include <cuda_runtime.h>
#include <cuda_bf16.h>
#include <cstdint>

#define NC          18
#define TPB         256
#define TILE_PAIRS  256
#define PAIR_BYTES  144                          // 2 rows * 18 floats * 4B
#define TILE_BYTES  (TILE_PAIRS * PAIR_BYTES)    // 36864 per tensor
#define STAGE_BYTES (2 * TILE_BYTES)             // X tile + L tile = 73728
#define NSTAGES     2
#define SMEM_BYTES  (NSTAGES * STAGE_BYTES)      // 147456

__device__ float        g_partials[2048];
__device__ unsigned int g_count = 0;

// ---------------- PTX helpers ----------------
__device__ __forceinline__ unsigned smem_u32(const void* p) {
    return (unsigned)__cvta_generic_to_shared(p);
}
__device__ __forceinline__ void mbar_init(unsigned a, unsigned c) {
    asm volatile("mbarrier.init.shared.b64 [%0], %1;" :: "r"(a), "r"(c) : "memory");
}
__device__ __forceinline__ void fence_proxy_async_s() {
    asm volatile("fence.proxy.async.shared::cta;" ::: "memory");
}
__device__ __forceinline__ void mbar_expect_tx(unsigned a, unsigned bytes) {
    asm volatile("mbarrier.arrive.expect_tx.shared.b64 _, [%0], %1;"
                 :: "r"(a), "r"(bytes) : "memory");
}
__device__ __forceinline__ void bulk_g2s(unsigned dst, const void* src,
                                         unsigned bytes, unsigned bar) {
    asm volatile(
        "cp.async.bulk.shared::cta.global.mbarrier::complete_tx::bytes [%0], [%1], %2, [%3];"
        :: "r"(dst), "l"(src), "r"(bytes), "r"(bar) : "memory");
}
__device__ __forceinline__ void mbar_wait(unsigned a, unsigned ph) {
    asm volatile(
        "{\n\t"
        ".reg .pred P;\n\t"
        "W%=:\n\t"
        "mbarrier.try_wait.parity.acquire.cta.shared::cta.b64 P, [%0], %1, 0x989680;\n\t"
        "@P bra D%=;\n\t"
        "bra W%=;\n\t"
        "D%=:\n\t"
        "}"
        :: "r"(a), "r"(ph) : "memory");
}

// loss(row) = (max + log(sum exp(x-max))) * sum(l) - sum(x*l)
__device__ __forceinline__ float row_loss18(const float* __restrict__ x,
                                            const float* __restrict__ l) {
    float m = x[0];
#pragma unroll
    for (int c = 1; c < NC; c++) m = fmaxf(m, x[c]);
    float s = 0.f;
#pragma unroll
    for (int c = 0; c < NC; c++) s += __expf(x[c] - m);
    float sl = 0.f, sxl = 0.f;
#pragma unroll
    for (int c = 0; c < NC; c++) { sl += l[c]; sxl = fmaf(x[c], l[c], sxl); }
    return (m + __logf(s)) * sl - sxl;
}

extern __shared__ __align__(128) unsigned char smem_dyn[];

__global__ __launch_bounds__(TPB, 1)
void ce_main(const float* __restrict__ X, const float* __restrict__ L,
             float* __restrict__ out,
             int pairs, int ntiles, int odd, float inv_b)
{
    __shared__ uint64_t mbar_s[NSTAGES];
    __shared__ float    red[TPB / 32];
    __shared__ unsigned last_flag;

    const int tid = threadIdx.x;
    const int bid = blockIdx.x;
    const int G   = gridDim.x;

    // Balanced contiguous tile range per block.
    const int q = ntiles / G, r = ntiles % G;
    const int my_n     = q + (bid < r ? 1 : 0);
    const int my_first = bid * q + min(bid, r);

    unsigned bar[NSTAGES];
#pragma unroll
    for (int s = 0; s < NSTAGES; s++) bar[s] = smem_u32(&mbar_s[s]);

    if (tid == 0) {
#pragma unroll
        for (int s = 0; s < NSTAGES; s++) mbar_init(bar[s], 1);
        fence_proxy_async_s();
    }
    __syncthreads();

    auto prefetch = [&](int tile, int s) {
        int cnt = min(TILE_PAIRS, pairs - tile * TILE_PAIRS);
        unsigned bytes = (unsigned)cnt * PAIR_BYTES;
        unsigned dstx  = smem_u32(smem_dyn) + (unsigned)(s * STAGE_BYTES);
        unsigned dstl  = dstx + TILE_BYTES;
        const char* srcx = (const char*)X + (size_t)tile * TILE_BYTES;
        const char* srcl = (const char*)L + (size_t)tile * TILE_BYTES;
        mbar_expect_tx(bar[s], 2u * bytes);
        bulk_g2s(dstx, srcx, bytes, bar[s]);
        bulk_g2s(dstl, srcl, bytes, bar[s]);
    };

    if (tid == 0) {
        if (my_n > 0) prefetch(my_first, 0);
        if (my_n > 1) prefetch(my_first + 1, 1);
    }

    unsigned ph0 = 0, ph1 = 0;
    float acc = 0.f;

    for (int i = 0; i < my_n; i++) {
        const int s = i & 1;
        if (s == 0) { mbar_wait(bar[0], ph0); ph0 ^= 1u; }
        else        { mbar_wait(bar[1], ph1); ph1 ^= 1u; }

        const int tile = my_first + i;
        const int cnt  = min(TILE_PAIRS, pairs - tile * TILE_PAIRS);

        if (tid < cnt) {
            const float4* xs4 = reinterpret_cast<const float4*>(
                smem_dyn + (size_t)s * STAGE_BYTES) + tid * 9;
            const float4* ls4 = reinterpret_cast<const float4*>(
                smem_dyn + (size_t)s * STAGE_BYTES + TILE_BYTES) + tid * 9;

            float x[36];
#pragma unroll
            for (int k = 0; k < 9; k++) {
                float4 v = xs4[k];
                x[4 * k + 0] = v.x; x[4 * k + 1] = v.y;
                x[4 * k + 2] = v.z; x[4 * k + 3] = v.w;
            }

            float m0 = x[0], m1 = x[18];
#pragma unroll
            for (int c = 1; c < NC; c++) {
                m0 = fmaxf(m0, x[c]);
                m1 = fmaxf(m1, x[18 + c]);
            }
            float s0 = 0.f, s1 = 0.f;
#pragma unroll
            for (int c = 0; c < NC; c++) {
                s0 += __expf(x[c] - m0);
                s1 += __expf(x[18 + c] - m1);
            }

            float sl0 = 0.f, sxl0 = 0.f, sl1 = 0.f, sxl1 = 0.f;
#pragma unroll
            for (int k = 0; k < 9; k++) {
                float4 v = ls4[k];
                float lv[4] = { v.x, v.y, v.z, v.w };
#pragma unroll
                for (int j = 0; j < 4; j++) {
                    int idx = 4 * k + j;
                    if (idx < NC) { sl0 += lv[j]; sxl0 = fmaf(x[idx], lv[j], sxl0); }
                    else          { sl1 += lv[j]; sxl1 = fmaf(x[idx], lv[j], sxl1); }
                }
            }

            acc += (m0 + __logf(s0)) * sl0 - sxl0
                 + (m1 + __logf(s1)) * sl1 - sxl1;
        }

        __syncthreads();   // everyone done reading stage s
        if (tid == 0 && i + 2 < my_n) prefetch(my_first + i + 2, s);
    }

    // Odd trailing row (B odd): handled once, straight from global.
    if (odd && bid == 0 && tid == 0) {
        size_t base = (size_t)pairs * (2 * NC);
        float x[NC], l[NC];
#pragma unroll
        for (int c = 0; c < NC; c++) { x[c] = X[base + c]; l[c] = L[base + c]; }
        acc += row_loss18(x, l);
    }

    // ---- deterministic block reduction ----
    const int lane = tid & 31, wid = tid >> 5;
#pragma unroll
    for (int o = 16; o > 0; o >>= 1) acc += __shfl_down_sync(0xffffffffu, acc, o);
    if (lane == 0) red[wid] = acc;
    __syncthreads();
    if (wid == 0) {
        float v = (lane < (TPB / 32)) ? red[lane] : 0.f;
#pragma unroll
        for (int o = 16; o > 0; o >>= 1) v += __shfl_down_sync(0xffffffffu, v, o);
        if (lane == 0) {
            g_partials[bid] = v;
            __threadfence();
            last_flag = (atomicAdd(&g_count, 1u) == (unsigned)(G - 1)) ? 1u : 0u;
        }
    }
    __syncthreads();

    // ---- last block folds the partials (fixed order -> deterministic) ----
    if (last_flag && wid == 0) {
        float v = 0.f;
        for (int i = lane; i < G; i += 32)
            v += ((volatile float*)g_partials)[i];
#pragma unroll
        for (int o = 16; o > 0; o >>= 1) v += __shfl_down_sync(0xffffffffu, v, o);
        if (lane == 0) {
            out[0]  = v * inv_b;
            g_count = 0;   // re-arm for next graph replay
        }
    }
}

extern "C" void kernel_launch(void* const* d_in, const int* in_sizes, int n_in,
                              void* d_out, int out_size) {
    const float* X = (const float*)d_in[0];   // output       [B, 18] f32
    const float* L = (const float*)d_in[1];   // labels_soft  [B, 18] f32
    float* out = (float*)d_out;

    long long total = in_sizes[0];
    long long B     = total / NC;
    int pairs  = (int)(B / 2);
    int odd    = (int)(B & 1);
    int ntiles = (pairs + TILE_PAIRS - 1) / TILE_PAIRS;

    int dev = 0;
    cudaGetDevice(&dev);
    int sms = 148;
    cudaDeviceGetAttribute(&sms, cudaDevAttrMultiProcessorCount, dev);
    int grid = sms;
    if (grid > 2048) grid = 2048;
    if (grid < 1) grid = 1;

    static int smem_set = 0;
    if (!smem_set) {
        cudaFuncSetAttribute(ce_main, cudaFuncAttributeMaxDynamicSharedMemorySize,
                             SMEM_BYTES);
        smem_set = 1;
    }

    ce_main<<<grid, TPB, SMEM_BYTES>>>(X, L, out, pairs, ntiles, odd,
                                       1.0f / (float)B);
}